// round 15
// baseline (speedup 1.0000x reference)
#include <cuda_runtime.h>
#include <cuda_fp16.h>
#include <cuda_pipeline.h>
#include <mma.h>
#include <cstdint>
using namespace nvcuda;

#define BB 8
#define SS 4096
#define DD 1024
#define NTOK 32768
#define NSMALL 256
#define KPERM 3072
#define KOTH 2048
#define CHUNK 64
#define NCHUNK 64
#define TOTCHUNK 512

// ---------------- device scratch ----------------
__device__ __half  g_xhi[NTOK * DD];
__device__ __half  g_xlo[NTOK * DD];
__device__ __half  g_wperm[128 * KPERM];
__device__ __half  g_woth[128 * KOTH];
__device__ __half  g_wgate[DD * DD];
__device__ float   g_small[NTOK * NSMALL];
__device__ float   g_glogit[(size_t)NTOK * DD];
__device__ unsigned long long g_tpack[NTOK];
__device__ float   g_c[NTOK * 16];
__device__ float   g_b[NTOK * 16];
__device__ unsigned long long g_Tc[TOTCHUNK];
__device__ float   g_Cc[TOTCHUNK * 16];
__device__ float   g_Bc[TOTCHUNK * 16];
__device__ float   g_hstart[TOTCHUNK * 16];
__device__ float   g_hs[NTOK * 16];

// ---------------- K0: x -> fp16 hi/lo split (4 float4 per thread) ----------------
__global__ void convert_x_kernel(const float* __restrict__ x) {
    int base = blockIdx.x * 1024 + threadIdx.x;
#pragma unroll
    for (int r = 0; r < 4; r++) {
        int i = base + r * 256;
        float4 v = ((const float4*)x)[i];
        __half h0 = __float2half_rn(v.x), h1 = __float2half_rn(v.y);
        __half h2 = __float2half_rn(v.z), h3 = __float2half_rn(v.w);
        __half l0 = __float2half_rn(v.x - __half2float(h0));
        __half l1 = __float2half_rn(v.y - __half2float(h1));
        __half l2 = __float2half_rn(v.z - __half2float(h2));
        __half l3 = __float2half_rn(v.w - __half2float(h3));
        __half2* hi2 = (__half2*)g_xhi;  __half2* lo2 = (__half2*)g_xlo;
        hi2[i*2+0] = __halves2half2(h0,h1); hi2[i*2+1] = __halves2half2(h2,h3);
        lo2[i*2+0] = __halves2half2(l0,l1); lo2[i*2+1] = __halves2half2(l2,l3);
    }
}

// ---------------- merged weight convert ----------------
#define WPERM_END (128 * KPERM)
#define WOTH_END  (WPERM_END + 128 * KOTH)
#define WALL_END  (WOTH_END + DD * DD)
__global__ void convert_w_kernel(const float* __restrict__ wpr, const float* __restrict__ wpl,
                                 const float* __restrict__ wdr, const float* __restrict__ wdl,
                                 const float* __restrict__ war, const float* __restrict__ wal,
                                 const float* __restrict__ wb,  const float* __restrict__ wg) {
    int i = blockIdx.x * blockDim.x + threadIdx.x;
    if (i < WPERM_END) {
        int n = i / KPERM, k = i % KPERM;
        const float* src = (n < 64) ? (wpr + n * DD) : (wpl + (n - 64) * DD);
        float w = src[k & 1023];
        __half hi = __float2half_rn(w);
        __half out;
        if (k < 1024)      out = hi;
        else if (k < 2048) out = __float2half_rn(w - __half2float(hi));
        else               out = hi;
        g_wperm[i] = out;
    } else if (i < WOTH_END) {
        int j = i - WPERM_END;
        int n = j / KOTH, k = j % KOTH;
        const float* src = nullptr;
        if (n < 16)      src = wdr + n * DD;
        else if (n < 32) src = wdl + (n - 16) * DD;
        else if (n < 48) src = war + (n - 32) * DD;
        else if (n < 64) src = wal + (n - 48) * DD;
        else if (n < 80) src = wb  + (n - 64) * DD;
        g_woth[j] = src ? __float2half_rn(src[k & 1023]) : __float2half(0.0f);
    } else if (i < WALL_END) {
        int j = i - WOTH_END;
        g_wgate[j] = __float2half_rn(wg[j]);
    }
}

// ---------------- unified GEMM: C[M,N] = A[M,K] * W[N,K]^T ----------------
// BM=128 BN=128 BK=64, 3-stage cp.async (isolated test; no epilogue change),
// 256 thr, 8 warps (4x2), warp tile 32x64. smem 110.6KB x2 CTAs = 221KB <= 228KB.
#define BKH 64
#define LDH 72
#define STG_H (128 * LDH)
#define GEMM_SMEM (3 * STG_H * 2 * 2)   // 110592 B
__global__ void __launch_bounds__(256, 2) gemm_kernel(const __half* __restrict__ xhi,
                                                      const __half* __restrict__ xlo,
                                                      const __half* __restrict__ wperm,
                                                      const __half* __restrict__ woth,
                                                      const __half* __restrict__ wgt,
                                                      float* __restrict__ Csm,
                                                      float* __restrict__ Cgl) {
    extern __shared__ __half sh[];
    __half* As = sh;                 // [3][128][72]
    __half* Bs = sh + 3 * STG_H;     // [3][128][72]
    const int tid = threadIdx.x, wid = tid >> 5;
    const int wm = wid >> 1, wn = wid & 1;
    const int m0 = blockIdx.y * 128;
    const int bx = blockIdx.x;
    int KTOT, n0, bn0; const __half* Bw; bool is_gate = false;
    if (bx == 0)      { KTOT = KPERM; n0 = 0;   bn0 = 0; Bw = wperm; }
    else if (bx == 1) { KTOT = KOTH;  n0 = 128; bn0 = 0; Bw = woth; }
    else              { KTOT = DD; n0 = (bx - 2) * 128; bn0 = n0; Bw = wgt; is_gate = true; }
    const __half* segs[3];
    segs[0] = xhi;
    segs[1] = (bx == 1) ? xlo : xhi;
    segs[2] = xlo;

    wmma::fragment<wmma::accumulator, 16, 16, 16, float> acc[2][4];
#pragma unroll
    for (int i = 0; i < 2; i++)
#pragma unroll
        for (int j = 0; j < 4; j++) wmma::fill_fragment(acc[i][j], 0.0f);

    const int NK = KTOT / BKH;

    auto load_stage = [&](int kt, int st) {
        int kbase = kt * BKH;
        const __half* Ab = segs[kbase >> 10];
        int koff = kbase & 1023;
#pragma unroll
        for (int r = 0; r < 4; r++) {
            int i = tid + (r << 8);
            int rw = i >> 3, c = i & 7;
            __pipeline_memcpy_async(&As[st * STG_H + rw * LDH + (c << 3)],
                Ab + (size_t)(m0 + rw) * DD + koff + (c << 3), 16);
        }
#pragma unroll
        for (int r = 0; r < 4; r++) {
            int i = tid + (r << 8);
            int rw = i >> 3, c = i & 7;
            __pipeline_memcpy_async(&Bs[st * STG_H + rw * LDH + (c << 3)],
                Bw + (size_t)(bn0 + rw) * KTOT + kbase + (c << 3), 16);
        }
        __pipeline_commit();
    };

    load_stage(0, 0);
    if (NK > 1) load_stage(1, 1);
    int st = 0, ld = 2;              // stage of kt; stage to load next (no % in loop)
    for (int kt = 0; kt < NK; kt++) {
        __pipeline_wait_prior((kt + 1 < NK) ? 1 : 0);   // load(kt) complete
        __syncthreads();
        if (kt + 2 < NK) {
            load_stage(kt + 2, ld);
            if (++ld == 3) ld = 0;
        }
#pragma unroll
        for (int kk = 0; kk < 4; kk++) {
            wmma::fragment<wmma::matrix_a, 16, 16, 16, __half, wmma::row_major> af[2];
            wmma::fragment<wmma::matrix_b, 16, 16, 16, __half, wmma::col_major> bf[4];
#pragma unroll
            for (int i = 0; i < 2; i++)
                wmma::load_matrix_sync(af[i], &As[st * STG_H + (wm*32 + i*16) * LDH + kk*16], LDH);
#pragma unroll
            for (int j = 0; j < 4; j++)
                wmma::load_matrix_sync(bf[j], &Bs[st * STG_H + (wn*64 + j*16) * LDH + kk*16], LDH);
#pragma unroll
            for (int i = 0; i < 2; i++)
#pragma unroll
                for (int j = 0; j < 4; j++)
                    wmma::mma_sync(acc[i][j], af[i], bf[j], acc[i][j]);
        }
        if (++st == 3) st = 0;
    }

    if (!is_gate) {
#pragma unroll
        for (int i = 0; i < 2; i++)
#pragma unroll
            for (int j = 0; j < 4; j++)
                wmma::store_matrix_sync(Csm + (size_t)(m0 + wm*32 + i*16) * NSMALL + n0 + wn*64 + j*16,
                                        acc[i][j], NSMALL, wmma::mem_row_major);
    } else {
#pragma unroll
        for (int i = 0; i < 2; i++)
#pragma unroll
            for (int j = 0; j < 4; j++)
                wmma::store_matrix_sync(Cgl + (size_t)(m0 + wm*32 + i*16) * DD + n0 + wn*64 + j*16,
                                        acc[i][j], DD, wmma::mem_row_major);
    }
}

// ---------------- selection helpers ----------------
__device__ __forceinline__ float sel16f(const float* v, int i) {
    return (i & 8) ? ((i & 4) ? ((i & 2) ? ((i & 1) ? v[15] : v[14]) : ((i & 1) ? v[13] : v[12]))
                              : ((i & 2) ? ((i & 1) ? v[11] : v[10]) : ((i & 1) ? v[9]  : v[8])))
                   : ((i & 4) ? ((i & 2) ? ((i & 1) ? v[7]  : v[6])  : ((i & 1) ? v[5]  : v[4]))
                              : ((i & 2) ? ((i & 1) ? v[3]  : v[2])  : ((i & 1) ? v[1]  : v[0])));
}
__device__ __forceinline__ int sel16i(const int* v, int i) {
    return (i & 8) ? ((i & 4) ? ((i & 2) ? ((i & 1) ? v[15] : v[14]) : ((i & 1) ? v[13] : v[12]))
                              : ((i & 2) ? ((i & 1) ? v[11] : v[10]) : ((i & 1) ? v[9]  : v[8])))
                   : ((i & 4) ? ((i & 2) ? ((i & 1) ? v[7]  : v[6])  : ((i & 1) ? v[5]  : v[4]))
                              : ((i & 2) ? ((i & 1) ? v[3]  : v[2])  : ((i & 1) ? v[1]  : v[0])));
}

// ---------------- linear-domain Sinkhorn + argmax ----------------
__device__ __forceinline__ void sinkhorn_argmax_lin(float* p, int* idx) {
#pragma unroll
    for (int it = 0; it < 5; it++) {
#pragma unroll
        for (int i = 0; i < 4; i++) {
            float s = p[i*4] + p[i*4+1] + p[i*4+2] + p[i*4+3];
            float r = __fdividef(1.0f, s);
            p[i*4] *= r; p[i*4+1] *= r; p[i*4+2] *= r; p[i*4+3] *= r;
        }
        if (it < 4) {
#pragma unroll
            for (int j = 0; j < 4; j++) {
                float s = p[j] + p[4+j] + p[8+j] + p[12+j];
                float r = __fdividef(1.0f, s);
                p[j] *= r; p[4+j] *= r; p[8+j] *= r; p[12+j] *= r;
            }
        }
    }
#pragma unroll
    for (int j = 0; j < 4; j++) {
        int bi = 0; float bv = p[j];
        if (p[4+j]  > bv) { bv = p[4+j];  bi = 1; }
        if (p[8+j]  > bv) { bv = p[8+j];  bi = 2; }
        if (p[12+j] > bv) { bv = p[12+j]; bi = 3; }
        idx[j] = bi;
    }
}

__global__ void __launch_bounds__(64) factor_kernel(const float* __restrict__ mask) {
    int tok = blockIdx.x * 64 + threadIdx.x;
    if (tok >= NTOK) return;
    const float4* so4 = (const float4*)(g_small + (size_t)tok * NSMALL);
    int idxR[16], idxL[16];
    float a[16];
#pragma unroll
    for (int r = 0; r < 4; r++) {
#pragma unroll
        for (int e = 0; e < 4; e++) {
            float4 v = so4[r * 4 + e];
            a[e*4+0] = __expf(v.x * 2.0f); a[e*4+1] = __expf(v.y * 2.0f);
            a[e*4+2] = __expf(v.z * 2.0f); a[e*4+3] = __expf(v.w * 2.0f);
        }
        int id[4]; sinkhorn_argmax_lin(a, id);
#pragma unroll
        for (int j = 0; j < 4; j++) idxR[r*4+j] = id[j];
    }
#pragma unroll
    for (int r = 0; r < 4; r++) {
#pragma unroll
        for (int e = 0; e < 4; e++) {
            float4 v = so4[16 + r * 4 + e];
            a[e*4+0] = __expf(v.x * 2.0f); a[e*4+1] = __expf(v.y * 2.0f);
            a[e*4+2] = __expf(v.z * 2.0f); a[e*4+3] = __expf(v.w * 2.0f);
        }
        int id[4]; sinkhorn_argmax_lin(a, id);
#pragma unroll
        for (int j = 0; j < 4; j++) idxL[r*4+j] = id[j];
    }
    float dR[16], dL[16];
#pragma unroll
    for (int q = 0; q < 4; q++) {
        float4 td = so4[32 + q];
        float4 ta = so4[40 + q];
        dR[q*4+0] = __fdividef(1.0f, 1.0f + __expf(-ta.x)) * tanhf(td.x);
        dR[q*4+1] = __fdividef(1.0f, 1.0f + __expf(-ta.y)) * tanhf(td.y);
        dR[q*4+2] = __fdividef(1.0f, 1.0f + __expf(-ta.z)) * tanhf(td.z);
        dR[q*4+3] = __fdividef(1.0f, 1.0f + __expf(-ta.w)) * tanhf(td.w);
        float4 ud = so4[36 + q];
        float4 ua = so4[44 + q];
        dL[q*4+0] = __fdividef(1.0f, 1.0f + __expf(-ua.x)) * tanhf(ud.x);
        dL[q*4+1] = __fdividef(1.0f, 1.0f + __expf(-ua.y)) * tanhf(ud.y);
        dL[q*4+2] = __fdividef(1.0f, 1.0f + __expf(-ua.z)) * tanhf(ud.z);
        dL[q*4+3] = __fdividef(1.0f, 1.0f + __expf(-ua.w)) * tanhf(ud.w);
    }
    float bt[16];
#pragma unroll
    for (int q = 0; q < 4; q++) {
        float4 v = so4[48 + q];
        bt[q*4+0] = v.x; bt[q*4+1] = v.y; bt[q*4+2] = v.z; bt[q*4+3] = v.w;
    }
    float mk = mask[tok];
    unsigned long long tp = 0ull;
#pragma unroll
    for (int j = 0; j < 16; j++) {
        int r = j >> 2;
        int i1 = r*4 + idxR[j];
        int i2 = ((i1 & 3) << 2) | (i1 >> 2);
        int i3 = (i2 & ~3) + sel16i(idxL, i2);
        tp |= ((unsigned long long)i3) << (4*j);
        g_c[tok*16+j] = sel16f(dR, i1) * sel16f(dL, i3);
        g_b[tok*16+j] = bt[j] * mk;
    }
    g_tpack[tok] = tp;
}

// ---------------- chunked monomial scan ----------------
__global__ void scanA_kernel() {
    int wl = threadIdx.x >> 5, lane = threadIdx.x & 31, l = lane & 15;
    int gw = blockIdx.x * 8 + wl;
    __shared__ float sb[8][16];
    float* S = sb[wl];
    int base = (gw >> 6) * SS + (gw & 63) * CHUNK;
    int T = l; float C = 1.0f, Bv = 0.0f;
    for (int s = 0; s < CHUNK; s++) {
        int tok = base + s;
        unsigned long long tp = g_tpack[tok];
        int tj = (int)((tp >> (4*l)) & 15ull);
        float cj = g_c[tok*16+l], bj = g_b[tok*16+l];
        int   tT = __shfl_sync(0xffffffffu, tj, T);
        float cT = __shfl_sync(0xffffffffu, cj, T);
        if (lane < 16) S[l] = bj;
        __syncwarp();
        if (lane < 16) atomicAdd(&S[tj], cj * Bv);
        __syncwarp();
        if (lane < 16) Bv = S[l];
        __syncwarp();
        T = tT; C *= cT;
    }
    if (lane < 16) { g_Cc[gw*16+l] = C; g_Bc[gw*16+l] = Bv; }
    unsigned long long tpk = 0ull;
    for (int j = 0; j < 16; j++) {
        int v = __shfl_sync(0xffffffffu, T, j);
        tpk |= ((unsigned long long)(v & 15)) << (4*j);
    }
    if (lane == 0) g_Tc[gw] = tpk;
}

__global__ void scanB_kernel() {
    int wl = threadIdx.x >> 5, lane = threadIdx.x & 31, l = lane & 15;
    __shared__ float sb[8][16];
    float* S = sb[wl];
    float h = 0.0f;
    for (int k = 0; k < NCHUNK; k++) {
        int cid = wl * NCHUNK + k;
        if (lane < 16) g_hstart[cid*16+l] = h;
        unsigned long long tp = g_Tc[cid];
        int tj = (int)((tp >> (4*l)) & 15ull);
        float cj = g_Cc[cid*16+l], bj = g_Bc[cid*16+l];
        if (lane < 16) S[l] = bj;
        __syncwarp();
        if (lane < 16) atomicAdd(&S[tj], cj * h);
        __syncwarp();
        if (lane < 16) h = S[l];
        __syncwarp();
    }
}

__global__ void scanC_kernel() {
    int wl = threadIdx.x >> 5, lane = threadIdx.x & 31, l = lane & 15;
    int gw = blockIdx.x * 8 + wl;
    __shared__ float sb[8][16];
    float* S = sb[wl];
    int base = (gw >> 6) * SS + (gw & 63) * CHUNK;
    float h = (lane < 16) ? g_hstart[gw*16+l] : 0.0f;
    for (int s = 0; s < CHUNK; s++) {
        int tok = base + s;
        unsigned long long tp = g_tpack[tok];
        int tj = (int)((tp >> (4*l)) & 15ull);
        float cj = g_c[tok*16+l], bj = g_b[tok*16+l];
        if (lane < 16) S[l] = bj;
        __syncwarp();
        if (lane < 16) atomicAdd(&S[tj], cj * h);
        __syncwarp();
        if (lane < 16) { h = S[l]; g_hs[tok*16+l] = h; }
        __syncwarp();
    }
}

// ---------------- fused output with pipelined glogit loads ----------------
__global__ void __launch_bounds__(256) out_kernel(const float* __restrict__ WC,
                                                  const float* __restrict__ norm_w,
                                                  float* __restrict__ out) {
    __shared__ float sHS[16][17];
    __shared__ float ssum[16];
    const int tid = threadIdx.x;
    const int tok0 = blockIdx.x * 16;
    const int d0 = tid * 4;

    float4 wc4[4][4];
#pragma unroll
    for (int q = 0; q < 4; q++) {
        const float4* wr = (const float4*)(WC + (size_t)(d0 + q) * 16);
#pragma unroll
        for (int p = 0; p < 4; p++) wc4[q][p] = wr[p];
    }
    sHS[tid >> 4][tid & 15] = g_hs[(size_t)(tok0 + (tid >> 4)) * 16 + (tid & 15)];
    if (tid < 16) ssum[tid] = 0.0f;
    __syncthreads();

    const size_t base4 = ((size_t)tok0 * 1024 + d0) >> 2;
    float4 yv[16];
    float4 gl_next = ((const float4*)g_glogit)[base4];
#pragma unroll
    for (int t = 0; t < 16; t++) {
        float4 gl4 = gl_next;
        if (t < 15) gl_next = ((const float4*)g_glogit)[base4 + (t + 1) * 256];
        float hsr[16];
#pragma unroll
        for (int n = 0; n < 16; n++) hsr[n] = sHS[t][n];
        float glv[4] = {gl4.x, gl4.y, gl4.z, gl4.w};
        float* yp = (float*)&yv[t];
        float local = 0.0f;
#pragma unroll
        for (int q = 0; q < 4; q++) {
            float gate = __fdividef(1.0f, 1.0f + __expf(-glv[q]));
            float acc = 0.0f;
#pragma unroll
            for (int p = 0; p < 4; p++) {
                acc = fmaf(hsr[p*4+0], wc4[q][p].x, acc);
                acc = fmaf(hsr[p*4+1], wc4[q][p].y, acc);
                acc = fmaf(hsr[p*4+2], wc4[q][p].z, acc);
                acc = fmaf(hsr[p*4+3], wc4[q][p].w, acc);
            }
            float y = gate * acc;
            yp[q] = y;
            local = fmaf(y, y, local);
        }
        local += __shfl_down_sync(0xffffffffu, local, 16);
        local += __shfl_down_sync(0xffffffffu, local, 8);
        local += __shfl_down_sync(0xffffffffu, local, 4);
        local += __shfl_down_sync(0xffffffffu, local, 2);
        local += __shfl_down_sync(0xffffffffu, local, 1);
        if ((tid & 31) == 0) atomicAdd(&ssum[t], local);
    }
    __syncthreads();

    float4 nw4 = ((const float4*)norm_w)[tid];
#pragma unroll
    for (int t = 0; t < 16; t++) {
        float inv = rsqrtf(ssum[t] * (1.0f / 1024.0f) + 1e-6f);
        float4 v = yv[t];
        v.x *= inv * nw4.x; v.y *= inv * nw4.y;
        v.z *= inv * nw4.z; v.w *= inv * nw4.w;
        ((float4*)out)[base4 + t * 256] = v;
    }
}

// ---------------- launch ----------------
extern "C" void kernel_launch(void* const* d_in, const int* in_sizes, int n_in,
                              void* d_out, int out_size) {
    const float* x    = (const float*)d_in[0];
    const float* mask = (const float*)d_in[1];
    const float* wpr  = (const float*)d_in[2];
    const float* wdr  = (const float*)d_in[3];
    const float* war  = (const float*)d_in[4];
    const float* wpl  = (const float*)d_in[5];
    const float* wdl  = (const float*)d_in[6];
    const float* wal  = (const float*)d_in[7];
    const float* wb   = (const float*)d_in[8];
    const float* wc   = (const float*)d_in[9];
    const float* wg   = (const float*)d_in[10];
    const float* nw   = (const float*)d_in[11];
    float* out = (float*)d_out;

    cudaFuncSetAttribute(gemm_kernel, cudaFuncAttributeMaxDynamicSharedMemorySize, GEMM_SMEM);

    __half *xhi, *xlo, *wpm, *wot, *wgt; float *sm, *gl;
    cudaGetSymbolAddress((void**)&xhi, g_xhi);
    cudaGetSymbolAddress((void**)&xlo, g_xlo);
    cudaGetSymbolAddress((void**)&wpm, g_wperm);
    cudaGetSymbolAddress((void**)&wot, g_woth);
    cudaGetSymbolAddress((void**)&wgt, g_wgate);
    cudaGetSymbolAddress((void**)&sm,  g_small);
    cudaGetSymbolAddress((void**)&gl,  g_glogit);

    convert_x_kernel<<<NTOK * DD / 4 / 1024, 256>>>(x);
    convert_w_kernel<<<(WALL_END + 255) / 256, 256>>>(wpr, wpl, wdr, wdl, war, wal, wb, wg);

    dim3 gall(10, NTOK / 128);   // bx0: perm; bx1: other; bx2-9: gate
    gemm_kernel<<<gall, 256, GEMM_SMEM>>>(xhi, xlo, wpm, wot, wgt, sm, gl);

    factor_kernel<<<NTOK / 64, 64>>>(mask);
    scanA_kernel<<<TOTCHUNK / 8, 256>>>();
    scanB_kernel<<<1, 256>>>();
    scanC_kernel<<<TOTCHUNK / 8, 256>>>();

    out_kernel<<<NTOK / 16, 256>>>(wc, nw, out);
}

// round 16
// speedup vs baseline: 1.0249x; 1.0249x over previous
#include <cuda_runtime.h>
#include <cuda_fp16.h>
#include <cuda_pipeline.h>
#include <mma.h>
#include <cstdint>
using namespace nvcuda;

#define BB 8
#define SS 4096
#define DD 1024
#define NTOK 32768
#define NSMALL 256
#define KPERM 3072
#define KOTH 2048
#define CHUNK 64
#define NCHUNK 64
#define TOTCHUNK 512

// ---------------- device scratch ----------------
__device__ __half  g_xhi[NTOK * DD];
__device__ __half  g_xlo[NTOK * DD];
__device__ __half  g_wperm[128 * KPERM];
__device__ __half  g_woth[128 * KOTH];
__device__ __half  g_wgate[DD * DD];
__device__ float   g_small[NTOK * NSMALL];
__device__ __half  g_glogit[(size_t)NTOK * DD];
__device__ unsigned long long g_tpack[NTOK];
__device__ float   g_c[NTOK * 16];
__device__ float   g_b[NTOK * 16];
__device__ unsigned long long g_Tc[TOTCHUNK];
__device__ float   g_Cc[TOTCHUNK * 16];
__device__ float   g_Bc[TOTCHUNK * 16];
__device__ float   g_hstart[TOTCHUNK * 16];
__device__ float   g_hs[NTOK * 16];

// ---------------- K0: x -> fp16 hi/lo split (2 float4 per thread, R14 config) ----------------
__global__ void convert_x_kernel(const float* __restrict__ x) {
    int base = blockIdx.x * 512 + threadIdx.x;
#pragma unroll
    for (int r = 0; r < 2; r++) {
        int i = base + r * 256;
        float4 v = ((const float4*)x)[i];
        __half h0 = __float2half_rn(v.x), h1 = __float2half_rn(v.y);
        __half h2 = __float2half_rn(v.z), h3 = __float2half_rn(v.w);
        __half l0 = __float2half_rn(v.x - __half2float(h0));
        __half l1 = __float2half_rn(v.y - __half2float(h1));
        __half l2 = __float2half_rn(v.z - __half2float(h2));
        __half l3 = __float2half_rn(v.w - __half2float(h3));
        __half2* hi2 = (__half2*)g_xhi;  __half2* lo2 = (__half2*)g_xlo;
        hi2[i*2+0] = __halves2half2(h0,h1); hi2[i*2+1] = __halves2half2(h2,h3);
        lo2[i*2+0] = __halves2half2(l0,l1); lo2[i*2+1] = __halves2half2(l2,l3);
    }
}

// ---------------- merged weight convert ----------------
#define WPERM_END (128 * KPERM)
#define WOTH_END  (WPERM_END + 128 * KOTH)
#define WALL_END  (WOTH_END + DD * DD)
__global__ void convert_w_kernel(const float* __restrict__ wpr, const float* __restrict__ wpl,
                                 const float* __restrict__ wdr, const float* __restrict__ wdl,
                                 const float* __restrict__ war, const float* __restrict__ wal,
                                 const float* __restrict__ wb,  const float* __restrict__ wg) {
    int i = blockIdx.x * blockDim.x + threadIdx.x;
    if (i < WPERM_END) {
        int n = i / KPERM, k = i % KPERM;
        const float* src = (n < 64) ? (wpr + n * DD) : (wpl + (n - 64) * DD);
        float w = src[k & 1023];
        __half hi = __float2half_rn(w);
        __half out;
        if (k < 1024)      out = hi;
        else if (k < 2048) out = __float2half_rn(w - __half2float(hi));
        else               out = hi;
        g_wperm[i] = out;
    } else if (i < WOTH_END) {
        int j = i - WPERM_END;
        int n = j / KOTH, k = j % KOTH;
        const float* src = nullptr;
        if (n < 16)      src = wdr + n * DD;
        else if (n < 32) src = wdl + (n - 16) * DD;
        else if (n < 48) src = war + (n - 32) * DD;
        else if (n < 64) src = wal + (n - 48) * DD;
        else if (n < 80) src = wb  + (n - 64) * DD;
        g_woth[j] = src ? __float2half_rn(src[k & 1023]) : __float2half(0.0f);
    } else if (i < WALL_END) {
        int j = i - WOTH_END;
        g_wgate[j] = __float2half_rn(wg[j]);
    }
}

// ---------------- unified GEMM: 2-stage BK=64 (settled config) ----------------
#define BKH 64
#define LDH 72
#define STG_H (128 * LDH)
#define GEMM_SMEM (2 * STG_H * 2 * 2)   // 73728 B
__global__ void __launch_bounds__(256, 2) gemm_kernel(const __half* __restrict__ xhi,
                                                      const __half* __restrict__ xlo,
                                                      const __half* __restrict__ wperm,
                                                      const __half* __restrict__ woth,
                                                      const __half* __restrict__ wgt,
                                                      float* __restrict__ Csm,
                                                      __half* __restrict__ Cgl) {
    extern __shared__ __half sh[];
    __half* As = sh;
    __half* Bs = sh + 2 * STG_H;
    const int tid = threadIdx.x, wid = tid >> 5;
    const int wm = wid >> 1, wn = wid & 1;
    const int m0 = blockIdx.y * 128;
    const int bx = blockIdx.x;
    int KTOT, n0, bn0; const __half* Bw; bool is_gate = false;
    if (bx == 0)      { KTOT = KPERM; n0 = 0;   bn0 = 0; Bw = wperm; }
    else if (bx == 1) { KTOT = KOTH;  n0 = 128; bn0 = 0; Bw = woth; }
    else              { KTOT = DD; n0 = (bx - 2) * 128; bn0 = n0; Bw = wgt; is_gate = true; }
    const __half* segs[3];
    segs[0] = xhi;
    segs[1] = (bx == 1) ? xlo : xhi;
    segs[2] = xlo;

    wmma::fragment<wmma::accumulator, 16, 16, 16, float> acc[2][4];
#pragma unroll
    for (int i = 0; i < 2; i++)
#pragma unroll
        for (int j = 0; j < 4; j++) wmma::fill_fragment(acc[i][j], 0.0f);

    const int NK = KTOT / BKH;

    auto load_stage = [&](int kt, int st) {
        int kbase = kt * BKH;
        const __half* Ab = segs[kbase >> 10];
        int koff = kbase & 1023;
#pragma unroll
        for (int r = 0; r < 4; r++) {
            int i = tid + (r << 8);
            int rw = i >> 3, c = i & 7;
            __pipeline_memcpy_async(&As[st * STG_H + rw * LDH + (c << 3)],
                Ab + (size_t)(m0 + rw) * DD + koff + (c << 3), 16);
        }
#pragma unroll
        for (int r = 0; r < 4; r++) {
            int i = tid + (r << 8);
            int rw = i >> 3, c = i & 7;
            __pipeline_memcpy_async(&Bs[st * STG_H + rw * LDH + (c << 3)],
                Bw + (size_t)(bn0 + rw) * KTOT + kbase + (c << 3), 16);
        }
        __pipeline_commit();
    };

    load_stage(0, 0);
    for (int kt = 0; kt < NK; kt++) {
        __pipeline_wait_prior(0);
        __syncthreads();
        if (kt + 1 < NK) load_stage(kt + 1, (kt + 1) & 1);
        int st = kt & 1;
#pragma unroll
        for (int kk = 0; kk < 4; kk++) {
            wmma::fragment<wmma::matrix_a, 16, 16, 16, __half, wmma::row_major> af[2];
            wmma::fragment<wmma::matrix_b, 16, 16, 16, __half, wmma::col_major> bf[4];
#pragma unroll
            for (int i = 0; i < 2; i++)
                wmma::load_matrix_sync(af[i], &As[st * STG_H + (wm*32 + i*16) * LDH + kk*16], LDH);
#pragma unroll
            for (int j = 0; j < 4; j++)
                wmma::load_matrix_sync(bf[j], &Bs[st * STG_H + (wn*64 + j*16) * LDH + kk*16], LDH);
#pragma unroll
            for (int i = 0; i < 2; i++)
#pragma unroll
                for (int j = 0; j < 4; j++)
                    wmma::mma_sync(acc[i][j], af[i], bf[j], acc[i][j]);
        }
    }

    if (!is_gate) {
#pragma unroll
        for (int i = 0; i < 2; i++)
#pragma unroll
            for (int j = 0; j < 4; j++)
                wmma::store_matrix_sync(Csm + (size_t)(m0 + wm*32 + i*16) * NSMALL + n0 + wn*64 + j*16,
                                        acc[i][j], NSMALL, wmma::mem_row_major);
    } else {
        // direct fp16 store: elementwise fp32->fp16 fragment copy (no smem, no syncs)
#pragma unroll
        for (int i = 0; i < 2; i++)
#pragma unroll
            for (int j = 0; j < 4; j++) {
                wmma::fragment<wmma::accumulator, 16, 16, 16, __half> hc;
#pragma unroll
                for (int e = 0; e < hc.num_elements; e++)
                    hc.x[e] = __float2half_rn(acc[i][j].x[e]);
                wmma::store_matrix_sync(Cgl + (size_t)(m0 + wm*32 + i*16) * DD + n0 + wn*64 + j*16,
                                        hc, DD, wmma::mem_row_major);
            }
    }
}

// ---------------- selection helpers ----------------
__device__ __forceinline__ float sel16f(const float* v, int i) {
    return (i & 8) ? ((i & 4) ? ((i & 2) ? ((i & 1) ? v[15] : v[14]) : ((i & 1) ? v[13] : v[12]))
                              : ((i & 2) ? ((i & 1) ? v[11] : v[10]) : ((i & 1) ? v[9]  : v[8])))
                   : ((i & 4) ? ((i & 2) ? ((i & 1) ? v[7]  : v[6])  : ((i & 1) ? v[5]  : v[4]))
                              : ((i & 2) ? ((i & 1) ? v[3]  : v[2])  : ((i & 1) ? v[1]  : v[0])));
}
__device__ __forceinline__ int sel16i(const int* v, int i) {
    return (i & 8) ? ((i & 4) ? ((i & 2) ? ((i & 1) ? v[15] : v[14]) : ((i & 1) ? v[13] : v[12]))
                              : ((i & 2) ? ((i & 1) ? v[11] : v[10]) : ((i & 1) ? v[9]  : v[8])))
                   : ((i & 4) ? ((i & 2) ? ((i & 1) ? v[7]  : v[6])  : ((i & 1) ? v[5]  : v[4]))
                              : ((i & 2) ? ((i & 1) ? v[3]  : v[2])  : ((i & 1) ? v[1]  : v[0])));
}

// ---------------- linear-domain Sinkhorn + argmax ----------------
__device__ __forceinline__ void sinkhorn_argmax_lin(float* p, int* idx) {
#pragma unroll
    for (int it = 0; it < 5; it++) {
#pragma unroll
        for (int i = 0; i < 4; i++) {
            float s = p[i*4] + p[i*4+1] + p[i*4+2] + p[i*4+3];
            float r = __fdividef(1.0f, s);
            p[i*4] *= r; p[i*4+1] *= r; p[i*4+2] *= r; p[i*4+3] *= r;
        }
        if (it < 4) {
#pragma unroll
            for (int j = 0; j < 4; j++) {
                float s = p[j] + p[4+j] + p[8+j] + p[12+j];
                float r = __fdividef(1.0f, s);
                p[j] *= r; p[4+j] *= r; p[8+j] *= r; p[12+j] *= r;
            }
        }
    }
#pragma unroll
    for (int j = 0; j < 4; j++) {
        int bi = 0; float bv = p[j];
        if (p[4+j]  > bv) { bv = p[4+j];  bi = 1; }
        if (p[8+j]  > bv) { bv = p[8+j];  bi = 2; }
        if (p[12+j] > bv) { bv = p[12+j]; bi = 3; }
        idx[j] = bi;
    }
}

__global__ void __launch_bounds__(64) factor_kernel(const float* __restrict__ mask) {
    int tok = blockIdx.x * 64 + threadIdx.x;
    if (tok >= NTOK) return;
    const float4* so4 = (const float4*)(g_small + (size_t)tok * NSMALL);
    int idxR[16], idxL[16];
    float a[16];
#pragma unroll
    for (int r = 0; r < 4; r++) {
#pragma unroll
        for (int e = 0; e < 4; e++) {
            float4 v = so4[r * 4 + e];
            a[e*4+0] = __expf(v.x * 2.0f); a[e*4+1] = __expf(v.y * 2.0f);
            a[e*4+2] = __expf(v.z * 2.0f); a[e*4+3] = __expf(v.w * 2.0f);
        }
        int id[4]; sinkhorn_argmax_lin(a, id);
#pragma unroll
        for (int j = 0; j < 4; j++) idxR[r*4+j] = id[j];
    }
#pragma unroll
    for (int r = 0; r < 4; r++) {
#pragma unroll
        for (int e = 0; e < 4; e++) {
            float4 v = so4[16 + r * 4 + e];
            a[e*4+0] = __expf(v.x * 2.0f); a[e*4+1] = __expf(v.y * 2.0f);
            a[e*4+2] = __expf(v.z * 2.0f); a[e*4+3] = __expf(v.w * 2.0f);
        }
        int id[4]; sinkhorn_argmax_lin(a, id);
#pragma unroll
        for (int j = 0; j < 4; j++) idxL[r*4+j] = id[j];
    }
    float dR[16], dL[16];
#pragma unroll
    for (int q = 0; q < 4; q++) {
        float4 td = so4[32 + q];
        float4 ta = so4[40 + q];
        dR[q*4+0] = __fdividef(1.0f, 1.0f + __expf(-ta.x)) * tanhf(td.x);
        dR[q*4+1] = __fdividef(1.0f, 1.0f + __expf(-ta.y)) * tanhf(td.y);
        dR[q*4+2] = __fdividef(1.0f, 1.0f + __expf(-ta.z)) * tanhf(td.z);
        dR[q*4+3] = __fdividef(1.0f, 1.0f + __expf(-ta.w)) * tanhf(td.w);
        float4 ud = so4[36 + q];
        float4 ua = so4[44 + q];
        dL[q*4+0] = __fdividef(1.0f, 1.0f + __expf(-ua.x)) * tanhf(ud.x);
        dL[q*4+1] = __fdividef(1.0f, 1.0f + __expf(-ua.y)) * tanhf(ud.y);
        dL[q*4+2] = __fdividef(1.0f, 1.0f + __expf(-ua.z)) * tanhf(ud.z);
        dL[q*4+3] = __fdividef(1.0f, 1.0f + __expf(-ua.w)) * tanhf(ud.w);
    }
    float bt[16];
#pragma unroll
    for (int q = 0; q < 4; q++) {
        float4 v = so4[48 + q];
        bt[q*4+0] = v.x; bt[q*4+1] = v.y; bt[q*4+2] = v.z; bt[q*4+3] = v.w;
    }
    float mk = mask[tok];
    unsigned long long tp = 0ull;
#pragma unroll
    for (int j = 0; j < 16; j++) {
        int r = j >> 2;
        int i1 = r*4 + idxR[j];
        int i2 = ((i1 & 3) << 2) | (i1 >> 2);
        int i3 = (i2 & ~3) + sel16i(idxL, i2);
        tp |= ((unsigned long long)i3) << (4*j);
        g_c[tok*16+j] = sel16f(dR, i1) * sel16f(dL, i3);
        g_b[tok*16+j] = bt[j] * mk;
    }
    g_tpack[tok] = tp;
}

// ---------------- chunked monomial scan ----------------
__global__ void scanA_kernel() {
    int wl = threadIdx.x >> 5, lane = threadIdx.x & 31, l = lane & 15;
    int gw = blockIdx.x * 8 + wl;
    __shared__ float sb[8][16];
    float* S = sb[wl];
    int base = (gw >> 6) * SS + (gw & 63) * CHUNK;
    int T = l; float C = 1.0f, Bv = 0.0f;
    for (int s = 0; s < CHUNK; s++) {
        int tok = base + s;
        unsigned long long tp = g_tpack[tok];
        int tj = (int)((tp >> (4*l)) & 15ull);
        float cj = g_c[tok*16+l], bj = g_b[tok*16+l];
        int   tT = __shfl_sync(0xffffffffu, tj, T);
        float cT = __shfl_sync(0xffffffffu, cj, T);
        if (lane < 16) S[l] = bj;
        __syncwarp();
        if (lane < 16) atomicAdd(&S[tj], cj * Bv);
        __syncwarp();
        if (lane < 16) Bv = S[l];
        __syncwarp();
        T = tT; C *= cT;
    }
    if (lane < 16) { g_Cc[gw*16+l] = C; g_Bc[gw*16+l] = Bv; }
    unsigned long long tpk = 0ull;
    for (int j = 0; j < 16; j++) {
        int v = __shfl_sync(0xffffffffu, T, j);
        tpk |= ((unsigned long long)(v & 15)) << (4*j);
    }
    if (lane == 0) g_Tc[gw] = tpk;
}

__global__ void scanB_kernel() {
    int wl = threadIdx.x >> 5, lane = threadIdx.x & 31, l = lane & 15;
    __shared__ float sb[8][16];
    float* S = sb[wl];
    float h = 0.0f;
    for (int k = 0; k < NCHUNK; k++) {
        int cid = wl * NCHUNK + k;
        if (lane < 16) g_hstart[cid*16+l] = h;
        unsigned long long tp = g_Tc[cid];
        int tj = (int)((tp >> (4*l)) & 15ull);
        float cj = g_Cc[cid*16+l], bj = g_Bc[cid*16+l];
        if (lane < 16) S[l] = bj;
        __syncwarp();
        if (lane < 16) atomicAdd(&S[tj], cj * h);
        __syncwarp();
        if (lane < 16) h = S[l];
        __syncwarp();
    }
}

__global__ void scanC_kernel() {
    int wl = threadIdx.x >> 5, lane = threadIdx.x & 31, l = lane & 15;
    int gw = blockIdx.x * 8 + wl;
    __shared__ float sb[8][16];
    float* S = sb[wl];
    int base = (gw >> 6) * SS + (gw & 63) * CHUNK;
    float h = (lane < 16) ? g_hstart[gw*16+l] : 0.0f;
    for (int s = 0; s < CHUNK; s++) {
        int tok = base + s;
        unsigned long long tp = g_tpack[tok];
        int tj = (int)((tp >> (4*l)) & 15ull);
        float cj = g_c[tok*16+l], bj = g_b[tok*16+l];
        if (lane < 16) S[l] = bj;
        __syncwarp();
        if (lane < 16) atomicAdd(&S[tj], cj * h);
        __syncwarp();
        if (lane < 16) { h = S[l]; g_hs[tok*16+l] = h; }
        __syncwarp();
    }
}

// ---------------- fused output: fp16 glogit read, pipelined ----------------
__global__ void __launch_bounds__(256) out_kernel(const float* __restrict__ WC,
                                                  const float* __restrict__ norm_w,
                                                  float* __restrict__ out) {
    __shared__ float sHS[16][17];
    __shared__ float ssum[16];
    const int tid = threadIdx.x;
    const int tok0 = blockIdx.x * 16;
    const int d0 = tid * 4;

    float4 wc4[4][4];
#pragma unroll
    for (int q = 0; q < 4; q++) {
        const float4* wr = (const float4*)(WC + (size_t)(d0 + q) * 16);
#pragma unroll
        for (int p = 0; p < 4; p++) wc4[q][p] = wr[p];
    }
    sHS[tid >> 4][tid & 15] = g_hs[(size_t)(tok0 + (tid >> 4)) * 16 + (tid & 15)];
    if (tid < 16) ssum[tid] = 0.0f;
    __syncthreads();

    const size_t baseE = (size_t)tok0 * 1024 + d0;   // element index; +1024 per token
    float4 yv[16];
    uint2 gl_next = *(const uint2*)(g_glogit + baseE);
#pragma unroll
    for (int t = 0; t < 16; t++) {
        uint2 glu = gl_next;
        if (t < 15) gl_next = *(const uint2*)(g_glogit + baseE + (size_t)(t + 1) * 1024);
        __half2 g01 = *(__half2*)&glu.x, g23 = *(__half2*)&glu.y;
        float glv[4] = {__low2float(g01), __high2float(g01),
                        __low2float(g23), __high2float(g23)};
        float hsr[16];
#pragma unroll
        for (int n = 0; n < 16; n++) hsr[n] = sHS[t][n];
        float* yp = (float*)&yv[t];
        float local = 0.0f;
#pragma unroll
        for (int q = 0; q < 4; q++) {
            float gate = __fdividef(1.0f, 1.0f + __expf(-glv[q]));
            float acc = 0.0f;
#pragma unroll
            for (int p = 0; p < 4; p++) {
                acc = fmaf(hsr[p*4+0], wc4[q][p].x, acc);
                acc = fmaf(hsr[p*4+1], wc4[q][p].y, acc);
                acc = fmaf(hsr[p*4+2], wc4[q][p].z, acc);
                acc = fmaf(hsr[p*4+3], wc4[q][p].w, acc);
            }
            float y = gate * acc;
            yp[q] = y;
            local = fmaf(y, y, local);
        }
        local += __shfl_down_sync(0xffffffffu, local, 16);
        local += __shfl_down_sync(0xffffffffu, local, 8);
        local += __shfl_down_sync(0xffffffffu, local, 4);
        local += __shfl_down_sync(0xffffffffu, local, 2);
        local += __shfl_down_sync(0xffffffffu, local, 1);
        if ((tid & 31) == 0) atomicAdd(&ssum[t], local);
    }
    __syncthreads();

    float4 nw4 = ((const float4*)norm_w)[tid];
    const size_t base4 = baseE >> 2;
#pragma unroll
    for (int t = 0; t < 16; t++) {
        float inv = rsqrtf(ssum[t] * (1.0f / 1024.0f) + 1e-6f);
        float4 v = yv[t];
        v.x *= inv * nw4.x; v.y *= inv * nw4.y;
        v.z *= inv * nw4.z; v.w *= inv * nw4.w;
        ((float4*)out)[base4 + t * 256] = v;
    }
}

// ---------------- launch ----------------
extern "C" void kernel_launch(void* const* d_in, const int* in_sizes, int n_in,
                              void* d_out, int out_size) {
    const float* x    = (const float*)d_in[0];
    const float* mask = (const float*)d_in[1];
    const float* wpr  = (const float*)d_in[2];
    const float* wdr  = (const float*)d_in[3];
    const float* war  = (const float*)d_in[4];
    const float* wpl  = (const float*)d_in[5];
    const float* wdl  = (const float*)d_in[6];
    const float* wal  = (const float*)d_in[7];
    const float* wb   = (const float*)d_in[8];
    const float* wc   = (const float*)d_in[9];
    const float* wg   = (const float*)d_in[10];
    const float* nw   = (const float*)d_in[11];
    float* out = (float*)d_out;

    cudaFuncSetAttribute(gemm_kernel, cudaFuncAttributeMaxDynamicSharedMemorySize, GEMM_SMEM);

    __half *xhi, *xlo, *wpm, *wot, *wgt, *gl; float *sm;
    cudaGetSymbolAddress((void**)&xhi, g_xhi);
    cudaGetSymbolAddress((void**)&xlo, g_xlo);
    cudaGetSymbolAddress((void**)&wpm, g_wperm);
    cudaGetSymbolAddress((void**)&wot, g_woth);
    cudaGetSymbolAddress((void**)&wgt, g_wgate);
    cudaGetSymbolAddress((void**)&sm,  g_small);
    cudaGetSymbolAddress((void**)&gl,  g_glogit);

    convert_x_kernel<<<NTOK * DD / 4 / 512, 256>>>(x);
    convert_w_kernel<<<(WALL_END + 255) / 256, 256>>>(wpr, wpl, wdr, wdl, war, wal, wb, wg);

    dim3 gall(10, NTOK / 128);   // bx0: perm; bx1: other; bx2-9: gate
    gemm_kernel<<<gall, 256, GEMM_SMEM>>>(xhi, xlo, wpm, wot, wgt, sm, gl);

    factor_kernel<<<NTOK / 64, 64>>>(mask);
    scanA_kernel<<<TOTCHUNK / 8, 256>>>();
    scanB_kernel<<<1, 256>>>();
    scanC_kernel<<<TOTCHUNK / 8, 256>>>();

    out_kernel<<<NTOK / 16, 256>>>(wc, nw, out);
}